// round 6
// baseline (speedup 1.0000x reference)
#include <cuda_runtime.h>
#include <cstdint>

// Segment mean readout (HBM-bound stream, ~87% DRAM, overfetch ~0):
//   in0: atom_hiddens  float32 [1e6, 300]
//   in1: a_scope       int32   [50000, 2] (start, size), contiguous segments
//   out: mol_vecs      float32 [50000, 300]
//
// One warp per graph. Row = 75 float4 (1200 B). Lane l covers float4 cols
// l, l+32, l+64 (predicated l<11).
// Loads .lu (last-use), stores .cs (evict-first write-back) — best policy pair
// from R3-R5 sweep. This round: 4-row software pipeline (12 loads front-batched
// per turn) to deepen MLP 6->12 and lengthen DRAM bursts.

#define VEC_PER_ROW 75

__global__ void __launch_bounds__(256)
readout_mean_kernel(const float4* __restrict__ x,
                    const int* __restrict__ scope,
                    float4* __restrict__ out,
                    int n_graphs) {
    const int gwarp = (blockIdx.x * blockDim.x + threadIdx.x) >> 5;
    const int lane  = threadIdx.x & 31;
    if (gwarp >= n_graphs) return;

    const int start = scope[2 * gwarp];
    const int size  = scope[2 * gwarp + 1];

    float4 a0 = make_float4(0.f, 0.f, 0.f, 0.f);
    float4 a1 = make_float4(0.f, 0.f, 0.f, 0.f);
    float4 a2 = make_float4(0.f, 0.f, 0.f, 0.f);

    const bool has3 = (lane < VEC_PER_ROW - 64);  // lane < 11

    const float4* p = x + (long long)start * VEC_PER_ROW + lane;

    int r = 0;
    // 4-row pipeline: 12 independent last-use loads issued before any FADD retires.
    for (; r + 4 <= size; r += 4, p += 4 * VEC_PER_ROW) {
        const float4* q0 = p;
        const float4* q1 = p + VEC_PER_ROW;
        const float4* q2 = p + 2 * VEC_PER_ROW;
        const float4* q3 = p + 3 * VEC_PER_ROW;
        float4 v00 = __ldlu(q0);       float4 v01 = __ldlu(q0 + 32);
        float4 v10 = __ldlu(q1);       float4 v11 = __ldlu(q1 + 32);
        float4 v20 = __ldlu(q2);       float4 v21 = __ldlu(q2 + 32);
        float4 v30 = __ldlu(q3);       float4 v31 = __ldlu(q3 + 32);
        float4 v02, v12, v22, v32;
        if (has3) {
            v02 = __ldlu(q0 + 64);
            v12 = __ldlu(q1 + 64);
            v22 = __ldlu(q2 + 64);
            v32 = __ldlu(q3 + 64);
        }
        a0.x += v00.x; a0.y += v00.y; a0.z += v00.z; a0.w += v00.w;
        a1.x += v01.x; a1.y += v01.y; a1.z += v01.z; a1.w += v01.w;
        a0.x += v10.x; a0.y += v10.y; a0.z += v10.z; a0.w += v10.w;
        a1.x += v11.x; a1.y += v11.y; a1.z += v11.z; a1.w += v11.w;
        a0.x += v20.x; a0.y += v20.y; a0.z += v20.z; a0.w += v20.w;
        a1.x += v21.x; a1.y += v21.y; a1.z += v21.z; a1.w += v21.w;
        a0.x += v30.x; a0.y += v30.y; a0.z += v30.z; a0.w += v30.w;
        a1.x += v31.x; a1.y += v31.y; a1.z += v31.z; a1.w += v31.w;
        if (has3) {
            a2.x += v02.x; a2.y += v02.y; a2.z += v02.z; a2.w += v02.w;
            a2.x += v12.x; a2.y += v12.y; a2.z += v12.z; a2.w += v12.w;
            a2.x += v22.x; a2.y += v22.y; a2.z += v22.z; a2.w += v22.w;
            a2.x += v32.x; a2.y += v32.y; a2.z += v32.z; a2.w += v32.w;
        }
    }
    for (; r < size; ++r, p += VEC_PER_ROW) {
        float4 v0 = __ldlu(p);
        float4 v1 = __ldlu(p + 32);
        a0.x += v0.x; a0.y += v0.y; a0.z += v0.z; a0.w += v0.w;
        a1.x += v1.x; a1.y += v1.y; a1.z += v1.z; a1.w += v1.w;
        if (has3) {
            float4 v2 = __ldlu(p + 64);
            a2.x += v2.x; a2.y += v2.y; a2.z += v2.z; a2.w += v2.w;
        }
    }

    // denom = max(size,1); size==0 -> zeros (matches reference's where()).
    const float inv = (size > 0) ? (1.0f / (float)size) : 0.0f;

    float4* o = out + (long long)gwarp * VEC_PER_ROW + lane;
    __stcs(o,      make_float4(a0.x * inv, a0.y * inv, a0.z * inv, a0.w * inv));
    __stcs(o + 32, make_float4(a1.x * inv, a1.y * inv, a1.z * inv, a1.w * inv));
    if (has3) {
        __stcs(o + 64, make_float4(a2.x * inv, a2.y * inv, a2.z * inv, a2.w * inv));
    }
}

extern "C" void kernel_launch(void* const* d_in, const int* in_sizes, int n_in,
                              void* d_out, int out_size) {
    const float4* x = (const float4*)d_in[0];   // atom_hiddens f32 [1e6,300]
    const int* scope = (const int*)d_in[1];     // a_scope int32 [50000,2]
    float4* out = (float4*)d_out;

    const int n_graphs = in_sizes[1] / 2;       // 100000 ints -> 50000 graphs
    const int threads = 256;                    // 8 warps/block
    const int blocks = (n_graphs * 32 + threads - 1) / threads;

    readout_mean_kernel<<<blocks, threads>>>(x, scope, out, n_graphs);
}

// round 7
// speedup vs baseline: 1.0444x; 1.0444x over previous
#include <cuda_runtime.h>
#include <cstdint>

// Segment mean readout — FINAL (R5 config, best of session: 181.0us, 87.1% DRAM).
//   in0: atom_hiddens  float32 [1e6, 300]
//   in1: a_scope       int32   [50000, 2] (start, size), contiguous segments
//   out: mol_vecs      float32 [50000, 300]
//
// One warp per graph. Row = 75 float4 (1200 B). Lane l covers float4 cols
// l, l+32, l+64 (predicated l<11).
// Loads:  .lu (last-use — discard L2 line after the single read)
// Stores: .cs (evict-first write-back — keeps 128B dirty-line coalescing)
// 2-row pipeline (6 in-flight loads/warp): deeper batching regresses occupancy
// (R6: 12-load batch -> occ 56%->47%, DRAM 87%->83%). Traffic == irreducible
// 1.26 GB (overfetch ~0), so this is the access pattern's roofline.

#define VEC_PER_ROW 75

__global__ void __launch_bounds__(256)
readout_mean_kernel(const float4* __restrict__ x,
                    const int* __restrict__ scope,
                    float4* __restrict__ out,
                    int n_graphs) {
    const int gwarp = (blockIdx.x * blockDim.x + threadIdx.x) >> 5;
    const int lane  = threadIdx.x & 31;
    if (gwarp >= n_graphs) return;

    const int start = scope[2 * gwarp];
    const int size  = scope[2 * gwarp + 1];

    float4 a0 = make_float4(0.f, 0.f, 0.f, 0.f);
    float4 a1 = make_float4(0.f, 0.f, 0.f, 0.f);
    float4 a2 = make_float4(0.f, 0.f, 0.f, 0.f);

    const bool has3 = (lane < VEC_PER_ROW - 64);  // lane < 11

    const float4* p = x + (long long)start * VEC_PER_ROW + lane;

    int r = 0;
    // 2x software pipeline: 6 independent last-use loads in flight.
    for (; r + 2 <= size; r += 2, p += 2 * VEC_PER_ROW) {
        float4 v00 = __ldlu(p);
        float4 v01 = __ldlu(p + 32);
        float4 v10 = __ldlu(p + VEC_PER_ROW);
        float4 v11 = __ldlu(p + VEC_PER_ROW + 32);
        float4 v02, v12;
        if (has3) {
            v02 = __ldlu(p + 64);
            v12 = __ldlu(p + VEC_PER_ROW + 64);
        }
        a0.x += v00.x; a0.y += v00.y; a0.z += v00.z; a0.w += v00.w;
        a1.x += v01.x; a1.y += v01.y; a1.z += v01.z; a1.w += v01.w;
        a0.x += v10.x; a0.y += v10.y; a0.z += v10.z; a0.w += v10.w;
        a1.x += v11.x; a1.y += v11.y; a1.z += v11.z; a1.w += v11.w;
        if (has3) {
            a2.x += v02.x; a2.y += v02.y; a2.z += v02.z; a2.w += v02.w;
            a2.x += v12.x; a2.y += v12.y; a2.z += v12.z; a2.w += v12.w;
        }
    }
    for (; r < size; ++r, p += VEC_PER_ROW) {
        float4 v0 = __ldlu(p);
        float4 v1 = __ldlu(p + 32);
        a0.x += v0.x; a0.y += v0.y; a0.z += v0.z; a0.w += v0.w;
        a1.x += v1.x; a1.y += v1.y; a1.z += v1.z; a1.w += v1.w;
        if (has3) {
            float4 v2 = __ldlu(p + 64);
            a2.x += v2.x; a2.y += v2.y; a2.z += v2.z; a2.w += v2.w;
        }
    }

    // denom = max(size,1); size==0 -> zeros (matches reference's where()).
    const float inv = (size > 0) ? (1.0f / (float)size) : 0.0f;

    float4* o = out + (long long)gwarp * VEC_PER_ROW + lane;
    __stcs(o,      make_float4(a0.x * inv, a0.y * inv, a0.z * inv, a0.w * inv));
    __stcs(o + 32, make_float4(a1.x * inv, a1.y * inv, a1.z * inv, a1.w * inv));
    if (has3) {
        __stcs(o + 64, make_float4(a2.x * inv, a2.y * inv, a2.z * inv, a2.w * inv));
    }
}

extern "C" void kernel_launch(void* const* d_in, const int* in_sizes, int n_in,
                              void* d_out, int out_size) {
    const float4* x = (const float4*)d_in[0];   // atom_hiddens f32 [1e6,300]
    const int* scope = (const int*)d_in[1];     // a_scope int32 [50000,2]
    float4* out = (float4*)d_out;

    const int n_graphs = in_sizes[1] / 2;       // 100000 ints -> 50000 graphs
    const int threads = 256;                    // 8 warps/block
    const int blocks = (n_graphs * 32 + threads - 1) / threads;

    readout_mean_kernel<<<blocks, threads>>>(x, scope, out, n_graphs);
}